// round 8
// baseline (speedup 1.0000x reference)
#include <cuda_runtime.h>

#define TT 64
#define BB 1024
#define II 64
#define HH 256

// Scratch: hs[t][b][h] — first holds xW+biases, then overwritten in-place by the scan.
__device__ float g_hs[(size_t)TT * BB * HH];
// W_hh transposed: WT[k][h] = W_hh[h][k]  (coalesced RNN reads)
__device__ float g_WT[HH * HH];

typedef unsigned long long u64;

// ---- f32x2 packed helpers (sm_103a FFMA2 path, PTX-only) --------------------
#define FMA_F32X2(d, a, b, c) \
    asm("fma.rn.f32x2 %0, %1, %2, %3;" : "=l"(d) : "l"(a), "l"(b), "l"(c))
#define PACK_F32X2(out, lo, hi) \
    asm("mov.b64 %0, {%1, %2};" : "=l"(out) : "f"(lo), "f"(hi))
#define UNPACK_F32X2(lo, hi, in) \
    asm("mov.b64 {%0, %1}, %2;" : "=f"(lo), "=f"(hi) : "l"(in))

// ---------------------------------------------------------------------------
// Kernel 0: transpose W_hh (one-time, 256 KB)
// ---------------------------------------------------------------------------
__global__ void __launch_bounds__(256) wt_kernel(const float* __restrict__ W_hh)
{
    const int k = blockIdx.x;
    const int h = threadIdx.x;
    g_WT[k * HH + h] = W_hh[h * HH + k];
}

// ---------------------------------------------------------------------------
// Kernel 1: g_hs[t,b,h] = data[t,b,:] . W_ih[h,:] + b_ih[h] + b_hh[h]
// ---------------------------------------------------------------------------
__global__ void __launch_bounds__(256) xw_kernel(
    const float* __restrict__ data,
    const float* __restrict__ W_ih,
    const float* __restrict__ b_ih,
    const float* __restrict__ b_hh)
{
    __shared__ float sX[256];
    const int tid = threadIdx.x;
    const long r0 = (long)blockIdx.x * 64;

    float w[64];
    const float4* W4 = reinterpret_cast<const float4*>(W_ih) + tid * 16;
#pragma unroll
    for (int c = 0; c < 16; c++) {
        float4 v = W4[c];
        w[4*c+0] = v.x; w[4*c+1] = v.y; w[4*c+2] = v.z; w[4*c+3] = v.w;
    }
    const float bsum = b_ih[tid] + b_hh[tid];

    for (int rg = 0; rg < 16; rg++) {
        __syncthreads();
        sX[tid] = data[r0 * II + rg * 256 + tid];
        __syncthreads();
        float a0 = bsum, a1 = bsum, a2 = bsum, a3 = bsum;
        const float4* X4 = reinterpret_cast<const float4*>(sX);
#pragma unroll
        for (int c = 0; c < 16; c++) {
            float4 x;
            x = X4[c];      a0 += x.x*w[4*c] + x.y*w[4*c+1] + x.z*w[4*c+2] + x.w*w[4*c+3];
            x = X4[16+c];   a1 += x.x*w[4*c] + x.y*w[4*c+1] + x.z*w[4*c+2] + x.w*w[4*c+3];
            x = X4[32+c];   a2 += x.x*w[4*c] + x.y*w[4*c+1] + x.z*w[4*c+2] + x.w*w[4*c+3];
            x = X4[48+c];   a3 += x.x*w[4*c] + x.y*w[4*c+1] + x.z*w[4*c+2] + x.w*w[4*c+3];
        }
        long r = r0 + rg * 4;
        g_hs[(r+0)*HH + tid] = a0;
        g_hs[(r+1)*HH + tid] = a1;
        g_hs[(r+2)*HH + tid] = a2;
        g_hs[(r+3)*HH + tid] = a3;
    }
}

// ---------------------------------------------------------------------------
// Kernel 2: persistent RNN scan, transposed-W orientation (unchanged).
// ---------------------------------------------------------------------------
__global__ void __launch_bounds__(512) rnn_scan_kernel(
    const float* __restrict__ h0_in)
{
    __shared__ float hp[2][8][260];
    const int tid = threadIdx.x;
    const int bq = tid >> 6;
    const int hw = tid & 63;
    const int b0 = blockIdx.x * 8;
    const int bglob = b0 + bq;

    for (int m = tid; m < 2048; m += 512) {
        int bb = m >> 8, k = m & 255;
        hp[0][bb][k] = h0_in[(size_t)(b0 + bb) * HH + k];
    }
    __syncthreads();

    const ulonglong2* WT2 = reinterpret_cast<const ulonglong2*>(g_WT);

    for (int t = 0; t < TT; t++) {
        float* hs_row = g_hs + (size_t)t * BB * HH + (size_t)bglob * HH + hw * 4;
        const int rb = t & 1;

        float4 a0 = *reinterpret_cast<const float4*>(hs_row);
        u64 acc2[2];
        PACK_F32X2(acc2[0], a0.x, a0.y);
        PACK_F32X2(acc2[1], a0.z, a0.w);

        const float4* hp4 = reinterpret_cast<const float4*>(&hp[rb][bq][0]);

#pragma unroll 8
        for (int k4 = 0; k4 < 64; k4++) {
            float4 hv = hp4[k4];
            const ulonglong2* wr = WT2 + (size_t)(k4 * 4) * 64 + hw;
            ulonglong2 w0 = wr[0];
            ulonglong2 w1 = wr[64];
            ulonglong2 w2 = wr[128];
            ulonglong2 w3 = wr[192];
            u64 hd;
            PACK_F32X2(hd, hv.x, hv.x);
            FMA_F32X2(acc2[0], w0.x, hd, acc2[0]);
            FMA_F32X2(acc2[1], w0.y, hd, acc2[1]);
            PACK_F32X2(hd, hv.y, hv.y);
            FMA_F32X2(acc2[0], w1.x, hd, acc2[0]);
            FMA_F32X2(acc2[1], w1.y, hd, acc2[1]);
            PACK_F32X2(hd, hv.z, hv.z);
            FMA_F32X2(acc2[0], w2.x, hd, acc2[0]);
            FMA_F32X2(acc2[1], w2.y, hd, acc2[1]);
            PACK_F32X2(hd, hv.w, hv.w);
            FMA_F32X2(acc2[0], w3.x, hd, acc2[0]);
            FMA_F32X2(acc2[1], w3.y, hd, acc2[1]);
        }

        float v0, v1, v2, v3;
        UNPACK_F32X2(v0, v1, acc2[0]);
        UNPACK_F32X2(v2, v3, acc2[1]);
        v0 = fmaxf(v0, 0.f); v1 = fmaxf(v1, 0.f);
        v2 = fmaxf(v2, 0.f); v3 = fmaxf(v3, 0.f);
        float4 vv = make_float4(v0, v1, v2, v3);
        *reinterpret_cast<float4*>(hs_row) = vv;
        *reinterpret_cast<float4*>(&hp[rb ^ 1][bq][hw * 4]) = vv;
        __syncthreads();
    }
}

// ---------------------------------------------------------------------------
// Kernel 3: attention. Grid = 2048 (2 blocks per b, 32 i-rows each).
// 256 threads: tid = iq*16 + hq. Thread owns i-pair (iA, iB) and the
// CONTIGUOUS h-chunk [16*hq, 16*hq+16) for scores, context and head.
// Single h-contiguous gather layout, double-buffered; all smem reads are
// LDS.128 yielding natural f32x2 h-pairs (zero packs in the scores loop).
// ---------------------------------------------------------------------------
#define GSH_STRIDE 264     // 256 h + 8 pad (words)

__global__ void __launch_bounds__(256, 2) attn_kernel(
    const int* __restrict__ nine_idx,
    const float* __restrict__ W_lin,
    const float* __restrict__ b_lin,
    float* __restrict__ out)
{
    __shared__ float Gsh[2][9 * GSH_STRIDE];
    __shared__ float sWl[512];
    __shared__ int   sidx[9];

    const int tid   = threadIdx.x;
    const int b     = blockIdx.x >> 1;
    const int ibase = (blockIdx.x & 1) * 32;
    const int iq    = tid >> 4;
    const int hq    = tid & 15;
    const int iA    = ibase + 2 * iq;
    const int iB    = iA + 1;
    const int hc    = 16 * hq;          // chunk base

    if (tid < 9) sidx[tid] = nine_idx[b * 9 + tid];
    sWl[tid] = W_lin[tid];
    sWl[256 + tid] = W_lin[256 + tid];
    __syncthreads();

    int idxr[9];
#pragma unroll
    for (int n = 0; n < 9; n++) idxr[n] = sidx[n];

    // H rows as packed h-pairs (contiguous chunk), loaded once
    u64 hspA[8], hspB[8];
    {
        const ulonglong2* HA = reinterpret_cast<const ulonglong2*>(
            g_hs + ((size_t)iA * BB + b) * HH + hc);
        const ulonglong2* HB = reinterpret_cast<const ulonglong2*>(
            g_hs + ((size_t)iB * BB + b) * HH + hc);
#pragma unroll
        for (int q = 0; q < 4; q++) {
            ulonglong2 va = HA[q];
            ulonglong2 vb = HB[q];
            hspA[2*q] = va.x; hspA[2*q+1] = va.y;
            hspB[2*q] = vb.x; hspB[2*q+1] = vb.y;
        }
    }

    // context accumulators over the same h-pairs
    u64 acc2A[8], acc2B[8];
#pragma unroll
    for (int e = 0; e < 8; e++) { acc2A[e] = 0ULL; acc2B[e] = 0ULL; }

    const float bl = b_lin[0];

    // prefetch gather rows for j = 0 (thread covers h = tid)
    float gr[9];
#pragma unroll
    for (int n = 0; n < 9; n++) {
        int iv = idxr[n];
        gr[n] = (iv < BB) ? g_hs[(size_t)iv * HH + tid] : 0.f;
    }

    float* out_attn = out + (size_t)TT * BB;

    for (int j = 0; j < TT; j++) {
        float* gh = Gsh[j & 1];
#pragma unroll
        for (int n = 0; n < 9; n++) gh[n * GSH_STRIDE + tid] = gr[n];
        __syncthreads();   // single barrier per j

        if (j < TT - 1) {
            const float* src = g_hs + (size_t)(j + 1) * BB * HH;
#pragma unroll
            for (int n = 0; n < 9; n++) {
                int iv = idxr[n];
                gr[n] = (iv < BB) ? src[(size_t)iv * HH + tid] : 0.f;
            }
        }

        // ---- scores: h-pair packed FMA2, LDS.128 reads, no packs ----
        float pA[9], pB[9];
#pragma unroll
        for (int n = 0; n < 9; n++) {
            const ulonglong2* gp = reinterpret_cast<const ulonglong2*>(
                gh + n * GSH_STRIDE + hc);
            u64 sA = 0ULL, sB = 0ULL;
#pragma unroll
            for (int q = 0; q < 4; q++) {
                ulonglong2 gq = gp[q];
                FMA_F32X2(sA, gq.x, hspA[2*q],   sA);
                FMA_F32X2(sB, gq.x, hspB[2*q],   sB);
                FMA_F32X2(sA, gq.y, hspA[2*q+1], sA);
                FMA_F32X2(sB, gq.y, hspB[2*q+1], sB);
            }
            float l0, l1;
            UNPACK_F32X2(l0, l1, sA); pA[n] = l0 + l1;
            UNPACK_F32X2(l0, l1, sB); pB[n] = l0 + l1;
        }

        // reduce the 16 hq-partials (lane bits 0..3)
#pragma unroll
        for (int n = 0; n < 9; n++) {
            float vA = pA[n], vB = pB[n];
            vA += __shfl_xor_sync(0xffffffffu, vA, 1);
            vA += __shfl_xor_sync(0xffffffffu, vA, 2);
            vA += __shfl_xor_sync(0xffffffffu, vA, 4);
            vA += __shfl_xor_sync(0xffffffffu, vA, 8);
            vB += __shfl_xor_sync(0xffffffffu, vB, 1);
            vB += __shfl_xor_sync(0xffffffffu, vB, 2);
            vB += __shfl_xor_sync(0xffffffffu, vB, 4);
            vB += __shfl_xor_sync(0xffffffffu, vB, 8);
            pA[n] = vA; pB[n] = vB;
        }

        // softmax over n (redundant across the 16 hq lanes)
        {
            float mA = pA[0], mB = pB[0];
#pragma unroll
            for (int n = 1; n < 9; n++) { mA = fmaxf(mA, pA[n]); mB = fmaxf(mB, pB[n]); }
            float sumA = 0.f, sumB = 0.f;
#pragma unroll
            for (int n = 0; n < 9; n++) {
                pA[n] = __expf(pA[n] - mA); sumA += pA[n];
                pB[n] = __expf(pB[n] - mB); sumB += pB[n];
            }
            float rA = 1.f / sumA, rB = 1.f / sumB;
#pragma unroll
            for (int n = 0; n < 9; n++) { pA[n] *= rA; pB[n] *= rB; }
        }

        // attn output (lanes hq<9 write one n for both i)
        if (hq < 9) {
            out_attn[(((size_t)(iA * TT + j)) * BB + b) * 9 + hq] = pA[hq];
            out_attn[(((size_t)(iB * TT + j)) * BB + b) * 9 + hq] = pB[hq];
        }

        // ---- masked context: same LDS.128 chunk reads, h-pair FMA2 ----
        if (j < iB) {
            const bool dA = (j < iA);
#pragma unroll
            for (int n = 0; n < 9; n++) {
                float vA = dA ? pA[n] : 0.f;
                u64 pdA, pdB;
                PACK_F32X2(pdA, vA, vA);
                PACK_F32X2(pdB, pB[n], pB[n]);
                const ulonglong2* gp = reinterpret_cast<const ulonglong2*>(
                    gh + n * GSH_STRIDE + hc);
#pragma unroll
                for (int q = 0; q < 4; q++) {
                    ulonglong2 gq = gp[q];
                    FMA_F32X2(acc2A[2*q],   pdA, gq.x, acc2A[2*q]);
                    FMA_F32X2(acc2A[2*q+1], pdA, gq.y, acc2A[2*q+1]);
                    FMA_F32X2(acc2B[2*q],   pdB, gq.x, acc2B[2*q]);
                    FMA_F32X2(acc2B[2*q+1], pdB, gq.y, acc2B[2*q+1]);
                }
            }
        }
    }

    // ---- head: pred[i,b] = relu([c_i, hs_i] . W_lin + b_lin); c_0 = hs_0 ----
#pragma unroll
    for (int i = 0; i < 2; i++) {
        const int gi = (i == 0) ? iA : iB;
        const u64* hsp = (i == 0) ? hspA : hspB;
        const u64* ac  = (i == 0) ? acc2A : acc2B;
        float t = 0.f;
#pragma unroll
        for (int e = 0; e < 8; e++) {
            const int h0 = hc + 2 * e;
            float h0v, h1v, a0v, a1v;
            UNPACK_F32X2(h0v, h1v, hsp[e]);
            UNPACK_F32X2(a0v, a1v, ac[e]);
            if (gi == 0) { a0v = h0v; a1v = h1v; }
            t += a0v * sWl[h0]     + h0v * sWl[256 + h0];
            t += a1v * sWl[h0 + 1] + h1v * sWl[256 + h0 + 1];
        }
        t += __shfl_xor_sync(0xffffffffu, t, 1);
        t += __shfl_xor_sync(0xffffffffu, t, 2);
        t += __shfl_xor_sync(0xffffffffu, t, 4);
        t += __shfl_xor_sync(0xffffffffu, t, 8);
        if (hq == 0)
            out[(size_t)gi * BB + b] = fmaxf(t + bl, 0.f);
    }
}

// ---------------------------------------------------------------------------
extern "C" void kernel_launch(void* const* d_in, const int* in_sizes, int n_in,
                              void* d_out, int out_size)
{
    const float* data  = (const float*)d_in[0];
    const int*   nidx  = (const int*)d_in[1];
    /* d_in[2] = haven_flag (always 0, branch unused) */
    const float* h0    = (const float*)d_in[3];
    const float* W_ih  = (const float*)d_in[4];
    const float* W_hh  = (const float*)d_in[5];
    const float* b_ih  = (const float*)d_in[6];
    const float* b_hh  = (const float*)d_in[7];
    const float* W_lin = (const float*)d_in[8];
    const float* b_lin = (const float*)d_in[9];
    float* out = (float*)d_out;

    (void)in_sizes; (void)n_in; (void)out_size;

    wt_kernel<<<256, 256>>>(W_hh);
    xw_kernel<<<1024, 256>>>(data, W_ih, b_ih, b_hh);
    rnn_scan_kernel<<<128, 512>>>(h0);
    attn_kernel<<<2048, 256>>>(nidx, W_lin, b_lin, out);
}

// round 9
// speedup vs baseline: 1.4482x; 1.4482x over previous
#include <cuda_runtime.h>

#define TT 64
#define BB 1024
#define II 64
#define HH 256

__device__ float g_hs[(size_t)TT * BB * HH];
__device__ float g_WT[HH * HH];   // WT[k][h] = W_hh[h][k]

typedef unsigned long long u64;

#define FMA_F32X2(d, a, b, c) \
    asm("fma.rn.f32x2 %0, %1, %2, %3;" : "=l"(d) : "l"(a), "l"(b), "l"(c))
#define PACK_F32X2(out, lo, hi) \
    asm("mov.b64 %0, {%1, %2};" : "=l"(out) : "f"(lo), "f"(hi))
#define UNPACK_F32X2(lo, hi, in) \
    asm("mov.b64 {%0, %1}, %2;" : "=f"(lo), "=f"(hi) : "l"(in))

// ---------------------------------------------------------------------------
// Kernel 0: transpose W_hh (one-time, 256 KB)
// ---------------------------------------------------------------------------
__global__ void __launch_bounds__(256) wt_kernel(const float* __restrict__ W_hh)
{
    const int k = blockIdx.x;
    const int h = threadIdx.x;
    g_WT[k * HH + h] = W_hh[h * HH + k];
}

// ---------------------------------------------------------------------------
// Kernel 1: g_hs[t,b,h] = data[t,b,:] . W_ih[h,:] + b_ih[h] + b_hh[h]
// ---------------------------------------------------------------------------
__global__ void __launch_bounds__(256) xw_kernel(
    const float* __restrict__ data,
    const float* __restrict__ W_ih,
    const float* __restrict__ b_ih,
    const float* __restrict__ b_hh)
{
    __shared__ float sX[256];
    const int tid = threadIdx.x;
    const long r0 = (long)blockIdx.x * 64;

    float w[64];
    const float4* W4 = reinterpret_cast<const float4*>(W_ih) + tid * 16;
#pragma unroll
    for (int c = 0; c < 16; c++) {
        float4 v = W4[c];
        w[4*c+0] = v.x; w[4*c+1] = v.y; w[4*c+2] = v.z; w[4*c+3] = v.w;
    }
    const float bsum = b_ih[tid] + b_hh[tid];

    for (int rg = 0; rg < 16; rg++) {
        __syncthreads();
        sX[tid] = data[r0 * II + rg * 256 + tid];
        __syncthreads();
        float a0 = bsum, a1 = bsum, a2 = bsum, a3 = bsum;
        const float4* X4 = reinterpret_cast<const float4*>(sX);
#pragma unroll
        for (int c = 0; c < 16; c++) {
            float4 x;
            x = X4[c];      a0 += x.x*w[4*c] + x.y*w[4*c+1] + x.z*w[4*c+2] + x.w*w[4*c+3];
            x = X4[16+c];   a1 += x.x*w[4*c] + x.y*w[4*c+1] + x.z*w[4*c+2] + x.w*w[4*c+3];
            x = X4[32+c];   a2 += x.x*w[4*c] + x.y*w[4*c+1] + x.z*w[4*c+2] + x.w*w[4*c+3];
            x = X4[48+c];   a3 += x.x*w[4*c] + x.y*w[4*c+1] + x.z*w[4*c+2] + x.w*w[4*c+3];
        }
        long r = r0 + rg * 4;
        g_hs[(r+0)*HH + tid] = a0;
        g_hs[(r+1)*HH + tid] = a1;
        g_hs[(r+2)*HH + tid] = a2;
        g_hs[(r+3)*HH + tid] = a3;
    }
}

// ---------------------------------------------------------------------------
// Kernel 2: persistent RNN scan, k-split. 128 blocks x 512 threads.
// Thread (kq = tid>>6 in [0,8), hw = tid&63): k-range [32kq, 32kq+32),
// h-slice = 4 contiguous h (hw*4). W is read ONCE per block per step
// (coalesced LDG.128, L2-resident). Partials for the 8 kq groups are summed
// through a 64 KB smem buffer; 2 barriers per step.
// ---------------------------------------------------------------------------
__global__ void __launch_bounds__(512) rnn_scan_kernel(
    const float* __restrict__ h0_in)
{
    extern __shared__ float sm[];
    float* hp   = sm;                 // [2][8][260]
    float* part = sm + 2 * 8 * 260;   // [8][2048]

    const int tid = threadIdx.x;
    const int kq = tid >> 6;          // 0..7
    const int hw = tid & 63;          // float4 column
    const int b0 = blockIdx.x * 8;

    for (int m = tid; m < 2048; m += 512) {
        int bb = m >> 8, k = m & 255;
        hp[bb * 260 + k] = h0_in[(size_t)(b0 + bb) * HH + k];
    }
    __syncthreads();

    // reduction-phase constants
    const int off = tid * 4;          // 0..2044
    const int rb_b = off >> 8;        // batch 0..7
    const int rb_h = off & 255;       // h

    for (int t = 0; t < TT; t++) {
        const int rb = t & 1;
        const float* hpc = hp + rb * 8 * 260;

        // partial GEMM over this thread's 32 k values
        u64 acc[8][2];
#pragma unroll
        for (int bb = 0; bb < 8; bb++) { acc[bb][0] = 0ULL; acc[bb][1] = 0ULL; }

#pragma unroll 2
        for (int k4 = 0; k4 < 8; k4++) {
            const int k = kq * 32 + k4 * 4;
            const ulonglong2* wr =
                reinterpret_cast<const ulonglong2*>(g_WT + (size_t)k * HH) + hw;
            ulonglong2 w0 = wr[0];
            ulonglong2 w1 = wr[64];
            ulonglong2 w2 = wr[128];
            ulonglong2 w3 = wr[192];
#pragma unroll
            for (int bb = 0; bb < 8; bb++) {
                float4 hv = *reinterpret_cast<const float4*>(hpc + bb * 260 + k);
                u64 hd;
                PACK_F32X2(hd, hv.x, hv.x);
                FMA_F32X2(acc[bb][0], w0.x, hd, acc[bb][0]);
                FMA_F32X2(acc[bb][1], w0.y, hd, acc[bb][1]);
                PACK_F32X2(hd, hv.y, hv.y);
                FMA_F32X2(acc[bb][0], w1.x, hd, acc[bb][0]);
                FMA_F32X2(acc[bb][1], w1.y, hd, acc[bb][1]);
                PACK_F32X2(hd, hv.z, hv.z);
                FMA_F32X2(acc[bb][0], w2.x, hd, acc[bb][0]);
                FMA_F32X2(acc[bb][1], w2.y, hd, acc[bb][1]);
                PACK_F32X2(hd, hv.w, hv.w);
                FMA_F32X2(acc[bb][0], w3.x, hd, acc[bb][0]);
                FMA_F32X2(acc[bb][1], w3.y, hd, acc[bb][1]);
            }
        }

        // write partials
#pragma unroll
        for (int bb = 0; bb < 8; bb++) {
            float f0, f1, f2, f3;
            UNPACK_F32X2(f0, f1, acc[bb][0]);
            UNPACK_F32X2(f2, f3, acc[bb][1]);
            *reinterpret_cast<float4*>(part + kq * 2048 + bb * 256 + hw * 4) =
                make_float4(f0, f1, f2, f3);
        }
        __syncthreads();

        // reduce 8 partials + xw bias, relu, store
        {
            float* hs_t = g_hs + (size_t)t * BB * HH;
            float4 r = *reinterpret_cast<const float4*>(
                hs_t + (size_t)(b0 + rb_b) * HH + rb_h);
#pragma unroll
            for (int q = 0; q < 8; q++) {
                float4 pv = *reinterpret_cast<const float4*>(part + q * 2048 + off);
                r.x += pv.x; r.y += pv.y; r.z += pv.z; r.w += pv.w;
            }
            r.x = fmaxf(r.x, 0.f); r.y = fmaxf(r.y, 0.f);
            r.z = fmaxf(r.z, 0.f); r.w = fmaxf(r.w, 0.f);
            *reinterpret_cast<float4*>(
                hs_t + (size_t)(b0 + rb_b) * HH + rb_h) = r;
            *reinterpret_cast<float4*>(
                hp + (rb ^ 1) * 8 * 260 + rb_b * 260 + rb_h) = r;
        }
        __syncthreads();
    }
}

// ---------------------------------------------------------------------------
// Kernel 3: attention. Grid = 1024 (one block per b, all 64 i-rows).
// 256 threads, __launch_bounds__(256,1) -> up to 255 regs, NO spills.
// tid = iq*16 + hq: thread owns i = 4*iq..4*iq+3 and contiguous h-chunk
// [16*hq, 16*hq+16). Gather staged h-contiguous (double-buffered, one barrier
// per j); all reads LDS.128 giving natural f32x2 pairs.
// ---------------------------------------------------------------------------
#define GSH_STRIDE 264

__global__ void __launch_bounds__(256, 1) attn_kernel(
    const int* __restrict__ nine_idx,
    const float* __restrict__ W_lin,
    const float* __restrict__ b_lin,
    float* __restrict__ out)
{
    __shared__ float Gsh[2][9 * GSH_STRIDE];
    __shared__ float sWl[512];
    __shared__ int   sidx[9];

    const int tid = threadIdx.x;
    const int b   = blockIdx.x;
    const int iq  = tid >> 4;      // 0..15
    const int hq  = tid & 15;      // 0..15
    const int i0  = 4 * iq;
    const int hc  = 16 * hq;

    if (tid < 9) sidx[tid] = nine_idx[b * 9 + tid];
    sWl[tid] = W_lin[tid];
    sWl[256 + tid] = W_lin[256 + tid];
    __syncthreads();

    int idxr[9];
#pragma unroll
    for (int n = 0; n < 9; n++) idxr[n] = sidx[n];

    // H rows as packed h-pairs: 4 i x 8 u64
    u64 hsp[4][8];
#pragma unroll
    for (int ii = 0; ii < 4; ii++) {
        const ulonglong2* H = reinterpret_cast<const ulonglong2*>(
            g_hs + ((size_t)(i0 + ii) * BB + b) * HH + hc);
#pragma unroll
        for (int q = 0; q < 4; q++) {
            ulonglong2 v = H[q];
            hsp[ii][2*q] = v.x; hsp[ii][2*q+1] = v.y;
        }
    }

    u64 acc[4][8];
#pragma unroll
    for (int ii = 0; ii < 4; ii++)
#pragma unroll
        for (int e = 0; e < 8; e++) acc[ii][e] = 0ULL;

    const float bl = b_lin[0];

    float gr[9];
#pragma unroll
    for (int n = 0; n < 9; n++) {
        int iv = idxr[n];
        gr[n] = (iv < BB) ? g_hs[(size_t)iv * HH + tid] : 0.f;
    }

    float* out_attn = out + (size_t)TT * BB;

    for (int j = 0; j < TT; j++) {
        float* gh = Gsh[j & 1];
#pragma unroll
        for (int n = 0; n < 9; n++) gh[n * GSH_STRIDE + tid] = gr[n];
        __syncthreads();

        if (j < TT - 1) {
            const float* src = g_hs + (size_t)(j + 1) * BB * HH;
#pragma unroll
            for (int n = 0; n < 9; n++) {
                int iv = idxr[n];
                gr[n] = (iv < BB) ? src[(size_t)iv * HH + tid] : 0.f;
            }
        }

        // ---- scores ----
        float p[4][9];
#pragma unroll
        for (int n = 0; n < 9; n++) {
            const ulonglong2* gp = reinterpret_cast<const ulonglong2*>(
                gh + n * GSH_STRIDE + hc);
            ulonglong2 gq0 = gp[0];
            ulonglong2 gq1 = gp[1];
            ulonglong2 gq2 = gp[2];
            ulonglong2 gq3 = gp[3];
#pragma unroll
            for (int ii = 0; ii < 4; ii++) {
                u64 s = 0ULL;
                FMA_F32X2(s, gq0.x, hsp[ii][0], s);
                FMA_F32X2(s, gq0.y, hsp[ii][1], s);
                FMA_F32X2(s, gq1.x, hsp[ii][2], s);
                FMA_F32X2(s, gq1.y, hsp[ii][3], s);
                FMA_F32X2(s, gq2.x, hsp[ii][4], s);
                FMA_F32X2(s, gq2.y, hsp[ii][5], s);
                FMA_F32X2(s, gq3.x, hsp[ii][6], s);
                FMA_F32X2(s, gq3.y, hsp[ii][7], s);
                float l0, l1;
                UNPACK_F32X2(l0, l1, s);
                p[ii][n] = l0 + l1;
            }
        }

        // reduce the 16 hq partials (lane bits 0..3)
#pragma unroll
        for (int ii = 0; ii < 4; ii++) {
#pragma unroll
            for (int n = 0; n < 9; n++) {
                float v = p[ii][n];
                v += __shfl_xor_sync(0xffffffffu, v, 1);
                v += __shfl_xor_sync(0xffffffffu, v, 2);
                v += __shfl_xor_sync(0xffffffffu, v, 4);
                v += __shfl_xor_sync(0xffffffffu, v, 8);
                p[ii][n] = v;
            }
        }

        // softmax over n (redundant across hq lanes)
#pragma unroll
        for (int ii = 0; ii < 4; ii++) {
            float m = p[ii][0];
#pragma unroll
            for (int n = 1; n < 9; n++) m = fmaxf(m, p[ii][n]);
            float sum = 0.f;
#pragma unroll
            for (int n = 0; n < 9; n++) { p[ii][n] = __expf(p[ii][n] - m); sum += p[ii][n]; }
            float r = 1.f / sum;
#pragma unroll
            for (int n = 0; n < 9; n++) p[ii][n] *= r;
        }

        // attn output
        if (hq < 9) {
#pragma unroll
            for (int ii = 0; ii < 4; ii++) {
                size_t base = (((size_t)((i0 + ii) * TT + j)) * BB + b) * 9 + hq;
                out_attn[base] = p[ii][hq];
            }
        }

        // ---- masked context (j < i) ----
        if (j < i0 + 3) {
#pragma unroll
            for (int n = 0; n < 9; n++) {
                const ulonglong2* gp = reinterpret_cast<const ulonglong2*>(
                    gh + n * GSH_STRIDE + hc);
                ulonglong2 gq0 = gp[0];
                ulonglong2 gq1 = gp[1];
                ulonglong2 gq2 = gp[2];
                ulonglong2 gq3 = gp[3];
#pragma unroll
                for (int ii = 0; ii < 4; ii++) {
                    float pv = (j < i0 + ii) ? p[ii][n] : 0.f;
                    if (ii == 3) pv = p[3][n];  // outer guard covers j < i0+3
                    u64 pd;
                    PACK_F32X2(pd, pv, pv);
                    FMA_F32X2(acc[ii][0], pd, gq0.x, acc[ii][0]);
                    FMA_F32X2(acc[ii][1], pd, gq0.y, acc[ii][1]);
                    FMA_F32X2(acc[ii][2], pd, gq1.x, acc[ii][2]);
                    FMA_F32X2(acc[ii][3], pd, gq1.y, acc[ii][3]);
                    FMA_F32X2(acc[ii][4], pd, gq2.x, acc[ii][4]);
                    FMA_F32X2(acc[ii][5], pd, gq2.y, acc[ii][5]);
                    FMA_F32X2(acc[ii][6], pd, gq3.x, acc[ii][6]);
                    FMA_F32X2(acc[ii][7], pd, gq3.y, acc[ii][7]);
                }
            }
        }
    }

    // ---- head ----
#pragma unroll
    for (int ii = 0; ii < 4; ii++) {
        const int gi = i0 + ii;
        float t = 0.f;
#pragma unroll
        for (int e = 0; e < 8; e++) {
            const int h0 = hc + 2 * e;
            float h0v, h1v, a0v, a1v;
            UNPACK_F32X2(h0v, h1v, hsp[ii][e]);
            UNPACK_F32X2(a0v, a1v, acc[ii][e]);
            if (gi == 0) { a0v = h0v; a1v = h1v; }
            t += a0v * sWl[h0]     + h0v * sWl[256 + h0];
            t += a1v * sWl[h0 + 1] + h1v * sWl[256 + h0 + 1];
        }
        t += __shfl_xor_sync(0xffffffffu, t, 1);
        t += __shfl_xor_sync(0xffffffffu, t, 2);
        t += __shfl_xor_sync(0xffffffffu, t, 4);
        t += __shfl_xor_sync(0xffffffffu, t, 8);
        if (hq == 0)
            out[(size_t)gi * BB + b] = fmaxf(t + bl, 0.f);
    }
}

// ---------------------------------------------------------------------------
extern "C" void kernel_launch(void* const* d_in, const int* in_sizes, int n_in,
                              void* d_out, int out_size)
{
    const float* data  = (const float*)d_in[0];
    const int*   nidx  = (const int*)d_in[1];
    /* d_in[2] = haven_flag (always 0, branch unused) */
    const float* h0    = (const float*)d_in[3];
    const float* W_ih  = (const float*)d_in[4];
    const float* W_hh  = (const float*)d_in[5];
    const float* b_ih  = (const float*)d_in[6];
    const float* b_hh  = (const float*)d_in[7];
    const float* W_lin = (const float*)d_in[8];
    const float* b_lin = (const float*)d_in[9];
    float* out = (float*)d_out;

    (void)in_sizes; (void)n_in; (void)out_size;

    wt_kernel<<<256, 256>>>(W_hh);
    xw_kernel<<<1024, 256>>>(data, W_ih, b_ih, b_hh);

    const int rnn_smem = (2 * 8 * 260 + 8 * 2048) * (int)sizeof(float);
    cudaFuncSetAttribute(rnn_scan_kernel,
                         cudaFuncAttributeMaxDynamicSharedMemorySize, rnn_smem);
    rnn_scan_kernel<<<128, 512, rnn_smem>>>(h0);

    attn_kernel<<<1024, 256>>>(nidx, W_lin, b_lin, out);
}